// round 5
// baseline (speedup 1.0000x reference)
#include <cuda_runtime.h>
#include <cstdint>

#define N_NODES 100000
#define HALF    50000
#define KK 5
#define CC 16
#define EE 3200000
#define PPK (EE / 4)                  // 800,000 int4-packs per k
#define PTOT (KK * PPK)               // 4,000,000 packs
#define NT 1024
#define ACC_BYTES (HALF * 4)          // 200,000 B fp32 accumulator

// Z transposed, fp32, k-major (2 MB, L2-resident).
__device__ float g_Zt[KK * N_NODES];

// Kernel 1: Z = X @ h (k-major), and zero y (d_out is poisoned).
__global__ __launch_bounds__(256) void compute_z_kernel(
    const float* __restrict__ X,
    const float* __restrict__ h,
    float* __restrict__ y)
{
    __shared__ float hs[CC * KK];
    if (threadIdx.x < CC * KK) hs[threadIdx.x] = h[threadIdx.x];
    __syncthreads();

    int n = blockIdx.x * blockDim.x + threadIdx.x;
    if (n >= N_NODES) return;

    float x[CC];
    const float4* xp = reinterpret_cast<const float4*>(X + (size_t)n * CC);
#pragma unroll
    for (int i = 0; i < CC / 4; i++) {
        float4 v = xp[i];
        x[4*i+0] = v.x; x[4*i+1] = v.y; x[4*i+2] = v.z; x[4*i+3] = v.w;
    }
#pragma unroll
    for (int k = 0; k < KK; k++) {
        float acc = 0.f;
#pragma unroll
        for (int c = 0; c < CC; c++) acc += x[c] * hs[c * KK + k];
        g_Zt[k * N_NODES + n] = acc;
    }
    y[n] = 0.f;
}

// Kernel 2: dual-backend scatter.
//   row <  HALF -> ATOMS into per-CTA smem accumulator (shared crossbar)
//   row >= HALF -> REDG straight to y (L1tex/L2 path)
// The two atomic streams run on independent backends and overlap.
// Gathers hit the L2-resident fp32 Zt slice via __ldg.
__global__ __launch_bounds__(NT, 1) void scatter_kernel(
    const int4*   __restrict__ rows,
    const int4*   __restrict__ cols,
    const float4* __restrict__ vals,
    float* __restrict__ y)
{
    extern __shared__ __align__(16) float sAcc[];   // [HALF]
    const int tid = threadIdx.x;

    // Zero the accumulator.
    {
        float4* a4 = reinterpret_cast<float4*>(sAcc);
        for (int i = tid; i < HALF / 4; i += NT)
            a4[i] = make_float4(0.f, 0.f, 0.f, 0.f);
    }
    __syncthreads();

    // Contiguous pack range for this CTA.
    long long bid = blockIdx.x, nb = gridDim.x;
    int p   = (int)((bid * PTOT) / nb);
    int end = (int)(((bid + 1) * PTOT) / nb);

    while (p < end) {
        int k    = p / PPK;
        int kend = (k + 1) * PPK; if (kend > end) kend = end;
        const float* __restrict__ Z = g_Zt + (size_t)k * N_NODES;

        for (int q = p + tid; q < kend; q += NT) {
            int4   r = __ldcg(rows + q);
            int4   c = __ldcg(cols + q);
            float4 v = __ldcg(vals + q);

            float z0 = __ldg(Z + c.x);
            float z1 = __ldg(Z + c.y);
            float z2 = __ldg(Z + c.z);
            float z3 = __ldg(Z + c.w);

            float s0 = v.x * z0;
            float s1 = v.y * z1;
            float s2 = v.z * z2;
            float s3 = v.w * z3;

            if (r.x < HALF) atomicAdd(sAcc + r.x, s0); else atomicAdd(y + r.x, s0);
            if (r.y < HALF) atomicAdd(sAcc + r.y, s1); else atomicAdd(y + r.y, s1);
            if (r.z < HALF) atomicAdd(sAcc + r.z, s2); else atomicAdd(y + r.z, s2);
            if (r.w < HALF) atomicAdd(sAcc + r.w, s3); else atomicAdd(y + r.w, s3);
        }
        p = kend;
    }

    // Flush accumulator (coalesced; skip exact zeros — adding 0 is a no-op).
    __syncthreads();
    for (int i = tid; i < HALF; i += NT) {
        float v = sAcc[i];
        if (v != 0.f) atomicAdd(y + i, v);
    }
}

extern "C" void kernel_launch(void* const* d_in, const int* in_sizes, int n_in,
                              void* d_out, int out_size) {
    const float* X    = (const float*)d_in[0];
    const int*   rows = (const int*)d_in[1];
    const int*   cols = (const int*)d_in[2];
    const float* vals = (const float*)d_in[3];
    const float* h    = (const float*)d_in[4];
    float* y = (float*)d_out;

    {
        int threads = 256;
        int blocks = (N_NODES + threads - 1) / threads;
        compute_z_kernel<<<blocks, threads>>>(X, h, y);
    }
    {
        static int sms = 0;
        if (sms == 0) {
            cudaDeviceGetAttribute(&sms, cudaDevAttrMultiProcessorCount, 0);
            if (sms <= 0) sms = 148;
            cudaFuncSetAttribute(scatter_kernel,
                                 cudaFuncAttributeMaxDynamicSharedMemorySize,
                                 ACC_BYTES);
        }
        scatter_kernel<<<sms, NT, ACC_BYTES>>>(
            (const int4*)rows, (const int4*)cols, (const float4*)vals, y);
    }
}